// round 15
// baseline (speedup 1.0000x reference)
#include <cuda_runtime.h>
#include <cuda_bf16.h>
#include <cuda_fp16.h>
#include <cstdint>

// Problem constants
#define NN   2048
#define BB   64
#define CC   64
#define DDIM 16
#define KORD 3

// -------------------- scratch (device globals) --------------------
__device__ __align__(16) __half g_Ah  [NN * NN];          // A (fp16)
__device__ __align__(16) __half g_Xh  [BB * NN * CC];     // X fp16 [b][n][c]
__device__ __align__(16) __half g_XG1h[BB * NN * CC];     // A @ X   fp16 [b][n][c]
__device__ __align__(16) __half g_XG2h[BB * NN * CC];     // T2 @ X  fp16 [b][n][c]
__device__ __align__(16) __half g_Wh  [NN * KORD * CC * CC]; // weights fp16 [n][k][i][o]

// ============================================================================
// portable PTX helpers
// ============================================================================
__device__ __forceinline__ uint32_t smem_u32(const void* p) {
    uint32_t a;
    asm("{ .reg .u64 t; cvta.to.shared.u64 t, %1; cvt.u32.u64 %0, t; }"
        : "=r"(a) : "l"(p));
    return a;
}

__device__ __forceinline__ void ldsm_x4(uint32_t addr, uint32_t* r) {
    asm volatile("ldmatrix.sync.aligned.m8n8.x4.shared.b16 {%0,%1,%2,%3}, [%4];"
                 : "=r"(r[0]), "=r"(r[1]), "=r"(r[2]), "=r"(r[3]) : "r"(addr));
}

// transposed load: B stored row-major [K][N] -> col-major fragments
__device__ __forceinline__ void ldsm_x4_t(uint32_t addr, uint32_t* r) {
    asm volatile("ldmatrix.sync.aligned.m8n8.x4.trans.shared.b16 {%0,%1,%2,%3}, [%4];"
                 : "=r"(r[0]), "=r"(r[1]), "=r"(r[2]), "=r"(r[3]) : "r"(addr));
}

__device__ __forceinline__ void mma_f16(float* d, const uint32_t* a, const uint32_t* b) {
    asm volatile("mma.sync.aligned.m16n8k16.row.col.f32.f16.f16.f32 "
                 "{%0,%1,%2,%3}, {%4,%5,%6,%7}, {%8,%9}, {%0,%1,%2,%3};"
                 : "+f"(d[0]), "+f"(d[1]), "+f"(d[2]), "+f"(d[3])
                 : "r"(a[0]), "r"(a[1]), "r"(a[2]), "r"(a[3]), "r"(b[0]), "r"(b[1]));
}

// f16-accumulate variant: D(f16x2 x2) = A*B + 0. Each k16 partial is rounded
// to fp16 exactly once, then promoted to the fp32 master accumulators.
__device__ __forceinline__ void mma_f16acc(float* m, const uint32_t* a, const uint32_t* b) {
    uint32_t d0, d1;
    asm volatile("mma.sync.aligned.m16n8k16.row.col.f16.f16.f16.f16 "
                 "{%0,%1}, {%2,%3,%4,%5}, {%6,%7}, {%8,%9};"
                 : "=r"(d0), "=r"(d1)
                 : "r"(a[0]), "r"(a[1]), "r"(a[2]), "r"(a[3]),
                   "r"(b[0]), "r"(b[1]), "r"(0u), "r"(0u));
    float2 lo = __half22float2(*reinterpret_cast<__half2*>(&d0));
    float2 hi = __half22float2(*reinterpret_cast<__half2*>(&d1));
    m[0] += lo.x; m[1] += lo.y; m[2] += hi.x; m[3] += hi.y;
}

__device__ __forceinline__ void cp_async16(uint32_t dst, const void* src) {
    asm volatile("cp.async.cg.shared.global [%0], [%1], 16;" :: "r"(dst), "l"(src));
}
#define CP_COMMIT() asm volatile("cp.async.commit_group;" ::: "memory")
#define CP_WAIT1()  asm volatile("cp.async.wait_group 1;" ::: "memory")
#define CP_WAIT0()  asm volatile("cp.async.wait_group 0;" ::: "memory")

// ============================================================================
// Kernel 1 (prep): blocks [0,512) supports, [512,4608) quant.
// ============================================================================
#define PREP_SUPP_BLOCKS  512           // NN/4
#define PREP_QUANT_BLOCKS 4096          // BB*NN*CC / (256*8)
#define PREP_BLOCKS (PREP_SUPP_BLOCKS + PREP_QUANT_BLOCKS)

__global__ __launch_bounds__(256)
void prep_kernel(const float* __restrict__ X,
                 const float* __restrict__ E)
{
    const int bid = blockIdx.x;
    const int t   = threadIdx.x;

    if (bid < PREP_SUPP_BLOCKS) {
        // ---------------- supports: A = softmax(relu(E E^T)) -> fp16 -------
        const int n0   = bid * 4;
        const int lane = t & 31;
        const int wid  = t >> 5;

        __shared__ float esh[4][DDIM];
        __shared__ float red[4][8];

        if (t < 64) esh[t >> 4][t & 15] = E[(n0 + (t >> 4)) * DDIM + (t & 15)];
        __syncthreads();

        float z[4][8];
#pragma unroll
        for (int j = 0; j < 8; ++j) {
            const int m = j * 256 + t;
            const float4* em = reinterpret_cast<const float4*>(E + m * DDIM);
            float4 v0 = __ldg(em + 0), v1 = __ldg(em + 1);
            float4 v2 = __ldg(em + 2), v3 = __ldg(em + 3);
#pragma unroll
            for (int r = 0; r < 4; ++r) {
                float s = esh[r][0]*v0.x + esh[r][1]*v0.y + esh[r][2]*v0.z + esh[r][3]*v0.w
                        + esh[r][4]*v1.x + esh[r][5]*v1.y + esh[r][6]*v1.z + esh[r][7]*v1.w
                        + esh[r][8]*v2.x + esh[r][9]*v2.y + esh[r][10]*v2.z + esh[r][11]*v2.w
                        + esh[r][12]*v3.x + esh[r][13]*v3.y + esh[r][14]*v3.z + esh[r][15]*v3.w;
                z[r][j] = fmaxf(s, 0.f);
            }
        }

#pragma unroll
        for (int r = 0; r < 4; ++r) {
            float v = z[r][0];
#pragma unroll
            for (int j = 1; j < 8; ++j) v = fmaxf(v, z[r][j]);
#pragma unroll
            for (int off = 16; off; off >>= 1)
                v = fmaxf(v, __shfl_xor_sync(0xffffffffu, v, off));
            if (lane == 0) red[r][wid] = v;
        }
        __syncthreads();
        float mx4[4];
#pragma unroll
        for (int r = 0; r < 4; ++r) {
            float v = red[r][0];
#pragma unroll
            for (int w = 1; w < 8; ++w) v = fmaxf(v, red[r][w]);
            mx4[r] = v;
        }
        __syncthreads();

        float sum4[4];
#pragma unroll
        for (int r = 0; r < 4; ++r) {
            float s = 0.f;
#pragma unroll
            for (int j = 0; j < 8; ++j) { z[r][j] = __expf(z[r][j] - mx4[r]); s += z[r][j]; }
#pragma unroll
            for (int off = 16; off; off >>= 1)
                s += __shfl_xor_sync(0xffffffffu, s, off);
            if (lane == 0) red[r][wid] = s;
        }
        __syncthreads();
#pragma unroll
        for (int r = 0; r < 4; ++r) {
            float s = red[r][0];
#pragma unroll
            for (int w = 1; w < 8; ++w) s += red[r][w];
            sum4[r] = s;
        }

#pragma unroll
        for (int r = 0; r < 4; ++r) {
            const float inv = 1.0f / sum4[r];
#pragma unroll
            for (int j = 0; j < 8; ++j)
                g_Ah[(size_t)(n0 + r) * NN + j * 256 + t] = __float2half_rn(z[r][j] * inv);
        }
    } else {
        // ---------------- quant: X fp32 -> fp16, same layout ---------------
        const int qb = bid - PREP_SUPP_BLOCKS;
        const size_t base = ((size_t)qb * 256 + t) * 8;
        float4 v0 = __ldg(reinterpret_cast<const float4*>(X + base));
        float4 v1 = __ldg(reinterpret_cast<const float4*>(X + base + 4));
        ushort4 h0;
        h0.x = __half_as_ushort(__float2half_rn(v0.x));
        h0.y = __half_as_ushort(__float2half_rn(v0.y));
        h0.z = __half_as_ushort(__float2half_rn(v0.z));
        h0.w = __half_as_ushort(__float2half_rn(v0.w));
        ushort4 h1;
        h1.x = __half_as_ushort(__float2half_rn(v1.x));
        h1.y = __half_as_ushort(__float2half_rn(v1.y));
        h1.z = __half_as_ushort(__float2half_rn(v1.z));
        h1.w = __half_as_ushort(__float2half_rn(v1.w));
        *reinterpret_cast<ushort4*>(g_Xh + base)     = h0;
        *reinterpret_cast<ushort4*>(g_Xh + base + 4) = h1;
    }
}

// ============================================================================
// Kernel 2 (x2): single-pass fp16 mma.sync GEMM, B via ldmatrix.trans.
//   MODE 0 uses f16-accumulate MMA (k16 partials promoted to fp32 masters)
//   to probe the HMMA f16-acc rate; MODE 1 keeps f32-accumulate.
//   MODE 0 also appends 768 wgen blocks filling idle wave-2 SMs.
// ============================================================================
#define G_SROWB     144                     // A smem row bytes: 128 + 16 pad
#define G_AMAT      (256 * G_SROWB)         // 36864 B
#define B_SROWB     272                     // B smem row bytes: 256 + 16 pad
#define G_BMAT      (64 * B_SROWB)          // 17408 B
#define G_STAGE     (G_AMAT + G_BMAT)       // 54272 B
#define GEMM_SMEM   (3 * G_STAGE)           // 162816 B

#define GEMM_TILES   256                    // 8 m-tiles x 32 batch-tiles
#define WGEN_BLOCKS  768                    // 64 n-groups x 12 chunks of 1024

template <int MODE>
__global__ __launch_bounds__(512, 1)
void gemm_kernel(const float* __restrict__ E, const float* __restrict__ Wp)
{
    extern __shared__ __align__(16) unsigned char smem_raw[];
    const uint32_t smem = smem_u32(smem_raw);

    const int bid = blockIdx.x;
    const int tid = threadIdx.x;

    if (MODE == 0 && bid >= GEMM_TILES) {
        // ---------------- wgen tail: W[n,k,i,o] = sum_d E[n,d]*Wp[d,k,i,o] --
        const int wb = bid - GEMM_TILES;
        const int n0 = (wb / 12) * 32;
        const int c0 = (wb % 12) * 1024;

        float (*WpS)[1024] = reinterpret_cast<float(*)[1024]>(smem_raw);
        float (*Es)[DDIM]  = reinterpret_cast<float(*)[DDIM]>(smem_raw + DDIM * 1024 * 4);

#pragma unroll
        for (int q = 0; q < 8; ++q) {
            const int idx = tid + q * 512;
            const int d = idx >> 8, c4 = idx & 255;
            cp_async16(smem + (uint32_t)(d * 1024 + c4 * 4) * 4,
                       Wp + (size_t)d * (KORD * CC * CC) + c0 + c4 * 4);
        }
        CP_COMMIT();
        if (tid < 128) {
            const int nl = tid >> 2, c4 = tid & 3;
            float4 v = __ldg(reinterpret_cast<const float4*>(
                E + (size_t)(n0 + nl) * DDIM + c4 * 4));
            Es[nl][c4*4+0] = v.x; Es[nl][c4*4+1] = v.y;
            Es[nl][c4*4+2] = v.z; Es[nl][c4*4+3] = v.w;
        }
        CP_WAIT0();
        __syncthreads();

#pragma unroll 4
        for (int q = 0; q < 64; ++q) {
            const int idx = tid + q * 512;
            const int nl = idx >> 10, c = idx & 1023;
            float s = 0.f;
#pragma unroll
            for (int d = 0; d < DDIM; ++d)
                s = fmaf(Es[nl][d], WpS[d][c], s);
            g_Wh[(size_t)(n0 + nl) * (KORD * CC * CC) + c0 + c] = __float2half_rn(s);
        }
        return;
    }

    // ---------------- GEMM tile ----------------
    const int lane = tid & 31;
    const int wid  = tid >> 5;
    const int m0   = (bid & 7) * 256;
    const int n0   = (bid >> 3) * 128;
    const int b0   = (bid >> 3) * 2;
    const int wm   = (wid >> 2) * 64;
    const int wn   = (wid & 3) * 32;

    const __half* __restrict__ Bhg = (MODE == 0) ? g_Xh : g_XG1h;

    float acc[4][4][4];
#pragma unroll
    for (int i = 0; i < 4; ++i)
#pragma unroll
        for (int j = 0; j < 4; ++j)
#pragma unroll
            for (int q = 0; q < 4; ++q) acc[i][j][q] = 0.f;

    auto issue = [&](int s) {
        const uint32_t sb = smem + (uint32_t)(s % 3) * G_STAGE;
        const int k0 = s * 64;
#pragma unroll
        for (int i = 0; i < 6; ++i) {
            const int idx = tid + i * 512;
            if (idx < 2048) {                      // A: rows 0..255, 8 chunks
                const int r = idx >> 3, c = idx & 7;
                cp_async16(sb + (uint32_t)(r * G_SROWB + c * 16),
                           g_Ah + (size_t)(m0 + r) * NN + k0 + c * 8);
            } else {                               // B: 64 k-rows x 16 chunks
                const int idx2 = idx - 2048;
                const int kl = idx2 >> 4;
                const int rem = idx2 & 15;
                const int b = rem >> 3, c8 = rem & 7;
                cp_async16(sb + (uint32_t)(G_AMAT + kl * B_SROWB + b * 128 + c8 * 16),
                           Bhg + ((size_t)(b0 + b) * NN + k0 + kl) * CC + c8 * 8);
            }
        }
        CP_COMMIT();
    };

    issue(0); issue(1);

    const uint32_t aRowB = (uint32_t)(wm + (lane & 15)) * G_SROWB
                         + (uint32_t)(lane >> 4) * 16;
    const uint32_t bRow  = (uint32_t)(lane & 15);
    const uint32_t bColB = (uint32_t)(wn + ((lane >> 4) << 3)) * 2;

    const int NT = NN / 64;   // 32

    for (int t = 0; t < NT; ++t) {
        CP_WAIT1();
        __syncthreads();

        const uint32_t sb = smem + (uint32_t)(t % 3) * G_STAGE;

        // ---- ks = 0 first, then overlap the next cp.async burst ----
        {
            uint32_t Af[4][4], Bf[2][4];
#pragma unroll
            for (int mt = 0; mt < 4; ++mt)
                ldsm_x4(sb + aRowB + (uint32_t)(mt * 16 * G_SROWB), Af[mt]);
#pragma unroll
            for (int bt = 0; bt < 2; ++bt)
                ldsm_x4_t(sb + G_AMAT + bRow * B_SROWB + bColB + (uint32_t)bt * 32, Bf[bt]);
#pragma unroll
            for (int mt = 0; mt < 4; ++mt)
#pragma unroll
                for (int nt = 0; nt < 4; ++nt) {
                    if (MODE == 0)
                        mma_f16acc(acc[mt][nt], Af[mt], &Bf[nt >> 1][(nt & 1) * 2]);
                    else
                        mma_f16(acc[mt][nt], Af[mt], &Bf[nt >> 1][(nt & 1) * 2]);
                }
        }

        if (t + 2 < NT) issue(t + 2);
        else CP_COMMIT();

#pragma unroll
        for (int ks = 1; ks < 4; ++ks) {
            const uint32_t kOff = (uint32_t)ks * 32;
            uint32_t Af[4][4], Bf[2][4];

#pragma unroll
            for (int mt = 0; mt < 4; ++mt)
                ldsm_x4(sb + aRowB + (uint32_t)(mt * 16 * G_SROWB) + kOff, Af[mt]);
#pragma unroll
            for (int bt = 0; bt < 2; ++bt)
                ldsm_x4_t(sb + G_AMAT + (uint32_t)(ks * 16 + bRow) * B_SROWB
                          + bColB + (uint32_t)bt * 32, Bf[bt]);
#pragma unroll
            for (int mt = 0; mt < 4; ++mt)
#pragma unroll
                for (int nt = 0; nt < 4; ++nt) {
                    if (MODE == 0)
                        mma_f16acc(acc[mt][nt], Af[mt], &Bf[nt >> 1][(nt & 1) * 2]);
                    else
                        mma_f16(acc[mt][nt], Af[mt], &Bf[nt >> 1][(nt & 1) * 2]);
                }
        }
    }

    // ---- epilogue: global fp16 writes ----
#pragma unroll
    for (int mt = 0; mt < 4; ++mt) {
        const int rloc = wm + mt * 16 + (lane >> 2);
        const int row  = m0 + rloc;
#pragma unroll
        for (int nt = 0; nt < 4; ++nt) {
            const int jloc = wn + nt * 8 + (lane & 3) * 2;
            const int j = n0 + jloc;
            const int b = j >> 6, c = j & 63;
            const size_t o0 = ((size_t)b * NN + row) * CC + c;
            const size_t o1 = ((size_t)b * NN + row + 8) * CC + c;
            if (MODE == 0) {
                *reinterpret_cast<__half2*>(g_XG1h + o0) =
                    __floats2half2_rn(acc[mt][nt][0], acc[mt][nt][1]);
                *reinterpret_cast<__half2*>(g_XG1h + o1) =
                    __floats2half2_rn(acc[mt][nt][2], acc[mt][nt][3]);
            } else {
                float2 x0 = __half22float2(*reinterpret_cast<const __half2*>(g_Xh + o0));
                float2 x1 = __half22float2(*reinterpret_cast<const __half2*>(g_Xh + o1));
                *reinterpret_cast<__half2*>(g_XG2h + o0) =
                    __floats2half2_rn(2.f * acc[mt][nt][0] - x0.x, 2.f * acc[mt][nt][1] - x0.y);
                *reinterpret_cast<__half2*>(g_XG2h + o1) =
                    __floats2half2_rn(2.f * acc[mt][nt][2] - x1.x, 2.f * acc[mt][nt][3] - x1.y);
            }
        }
    }
}

// ============================================================================
// Kernel 3: per-node contraction, single-pass fp16 tensor-core, cp.async loads.
// ============================================================================
#define F_SROW      200                    // Xs: fp16 per row (192 data + 8 pad)
#define F_XMATB     (64 * F_SROW * 2)      // 25600 B
#define F_WROWB     144                    // Ws row bytes: 128 data + 16 pad
#define F_WMATB     (192 * F_WROWB)        // 27648 B
#define FINAL_SMEM  (F_XMATB + F_WMATB)    // 53248 B

__global__ __launch_bounds__(256)
void final_kernel(const float* __restrict__ E,
                  const float* __restrict__ bp,
                  float* __restrict__ out)
{
    extern __shared__ __align__(16) unsigned char fsm_raw[];
    const uint32_t fsm = smem_u32(fsm_raw);
    const uint32_t XsA = fsm;               // [64 b][F_SROW i'] halves
    const uint32_t WsB = fsm + F_XMATB;     // [192 i'][64 o + pad] halves

    __shared__ float bias_s[CC];

    const int n    = blockIdx.x;
    const int tid  = threadIdx.x;
    const int lane = tid & 31;
    const int wid  = tid >> 5;

    // ---- Xcat: three fp16 sources via cp.async ----
    const __half* __restrict__ xsrcs[3] = { g_Xh, g_XG1h, g_XG2h };
#pragma unroll
    for (int k = 0; k < KORD; ++k) {
        const __half* __restrict__ hsrc = xsrcs[k];
#pragma unroll
        for (int i = 0; i < 2; ++i) {
            const int idx = tid + i * 256;
            const int b = idx >> 3, c8 = idx & 7;
            cp_async16(XsA + (uint32_t)(b * F_SROW + k * 64 + c8 * 8) * 2,
                       hsrc + ((size_t)b * NN + n) * CC + c8 * 8);
        }
    }
    // ---- W via cp.async into [i'][o] rows ----
#pragma unroll
    for (int k = 0; k < KORD; ++k) {
        const __half* wsrc = g_Wh + (size_t)n * (KORD * CC * CC) + (size_t)k * (CC * CC);
#pragma unroll
        for (int i = 0; i < 2; ++i) {
            const int idx = tid + i * 256;      // 64 ii x 8 chunks
            const int ii = idx >> 3, o8 = idx & 7;
            cp_async16(WsB + (uint32_t)((k * 64 + ii) * F_WROWB + o8 * 16),
                       wsrc + ii * 64 + o8 * 8);
        }
    }
    CP_COMMIT();

    if (tid < CC) {
        float s = 0.f;
#pragma unroll
        for (int d = 0; d < DDIM; ++d)
            s = fmaf(__ldg(E + (size_t)n * DDIM + d), __ldg(bp + d * CC + tid), s);
        bias_s[tid] = s;
    }
    CP_WAIT0();
    __syncthreads();

    const int wm    = (wid >> 1) * 16;     // b tile base
    const int obase = (wid & 1) * 32;      // o tile base

    const uint32_t aRowB = (uint32_t)(wm + (lane & 15)) * (F_SROW * 2)
                         + (uint32_t)(lane >> 4) * 16;
    const uint32_t bRow  = (uint32_t)(lane & 15);
    const uint32_t bColB = (uint32_t)(obase + ((lane >> 4) << 3)) * 2;

    float acc[4][4];
#pragma unroll
    for (int i = 0; i < 4; ++i)
#pragma unroll
        for (int q = 0; q < 4; ++q) acc[i][q] = 0.f;

#pragma unroll
    for (int step = 0; step < 12; ++step) {
        const uint32_t kOff = (uint32_t)step * 32;
        uint32_t Af[4], Bf[2][4];

        ldsm_x4(XsA + aRowB + kOff, Af);
#pragma unroll
        for (int bt = 0; bt < 2; ++bt)
            ldsm_x4_t(WsB + (uint32_t)(step * 16 + bRow) * F_WROWB
                      + bColB + (uint32_t)bt * 32, Bf[bt]);
#pragma unroll
        for (int nt = 0; nt < 4; ++nt)
            mma_f16(acc[nt], Af, &Bf[nt >> 1][(nt & 1) * 2]);
    }

    const int b0 = wm + (lane >> 2);
#pragma unroll
    for (int nt = 0; nt < 4; ++nt) {
        const int o = obase + nt * 8 + (lane & 3) * 2;
        const float bo0 = bias_s[o], bo1 = bias_s[o + 1];
        *reinterpret_cast<float2*>(out + ((size_t)b0 * NN + n) * CC + o) =
            make_float2(acc[nt][0] + bo0, acc[nt][1] + bo1);
        *reinterpret_cast<float2*>(out + ((size_t)(b0 + 8) * NN + n) * CC + o) =
            make_float2(acc[nt][2] + bo0, acc[nt][3] + bo1);
    }
}

// ============================================================================
// launch
// ============================================================================
extern "C" void kernel_launch(void* const* d_in, const int* in_sizes, int n_in,
                              void* d_out, int out_size)
{
    const float* X  = (const float*)d_in[0];
    const float* E  = (const float*)d_in[1];
    const float* Wp = (const float*)d_in[2];
    const float* bp = (const float*)d_in[3];
    float* out = (float*)d_out;

    cudaFuncSetAttribute(gemm_kernel<0>, cudaFuncAttributeMaxDynamicSharedMemorySize, GEMM_SMEM);
    cudaFuncSetAttribute(gemm_kernel<1>, cudaFuncAttributeMaxDynamicSharedMemorySize, GEMM_SMEM);
    cudaFuncSetAttribute(final_kernel, cudaFuncAttributeMaxDynamicSharedMemorySize, FINAL_SMEM);

    // 1. prep: adjacency + X quantization
    prep_kernel<<<PREP_BLOCKS, 256>>>(X, E);
    // 2. XG1 = A @ X  (f16-accumulate experiment) + wgen tail blocks
    gemm_kernel<0><<<GEMM_TILES + WGEN_BLOCKS, 512, GEMM_SMEM>>>(E, Wp);
    // 3. XG2 = 2 A @ XG1 - X  (f32-accumulate, unchanged)
    gemm_kernel<1><<<GEMM_TILES, 512, GEMM_SMEM>>>(E, Wp);
    // 4. per-node contraction + bias
    final_kernel<<<NN, 256, FINAL_SMEM>>>(E, bp, out);
}

// round 16
// speedup vs baseline: 1.2032x; 1.2032x over previous
#include <cuda_runtime.h>
#include <cuda_bf16.h>
#include <cuda_fp16.h>
#include <cstdint>

// Problem constants
#define NN   2048
#define BB   64
#define CC   64
#define DDIM 16
#define KORD 3

// -------------------- scratch (device globals) --------------------
__device__ __align__(16) __half g_Ah  [NN * NN];          // A (fp16)
__device__ __align__(16) __half g_Xh  [BB * NN * CC];     // X fp16 [b][n][c]
__device__ __align__(16) __half g_XG1h[BB * NN * CC];     // A @ X   fp16 [b][n][c]
__device__ __align__(16) __half g_XG2h[BB * NN * CC];     // T2 @ X  fp16 [b][n][c]
__device__ __align__(16) __half g_Wh  [NN * KORD * CC * CC]; // weights fp16 [n][k][i][o]

// ============================================================================
// portable PTX helpers
// ============================================================================
__device__ __forceinline__ uint32_t smem_u32(const void* p) {
    uint32_t a;
    asm("{ .reg .u64 t; cvta.to.shared.u64 t, %1; cvt.u32.u64 %0, t; }"
        : "=r"(a) : "l"(p));
    return a;
}

__device__ __forceinline__ void ldsm_x4(uint32_t addr, uint32_t* r) {
    asm volatile("ldmatrix.sync.aligned.m8n8.x4.shared.b16 {%0,%1,%2,%3}, [%4];"
                 : "=r"(r[0]), "=r"(r[1]), "=r"(r[2]), "=r"(r[3]) : "r"(addr));
}

// transposed load: B stored row-major [K][N] -> col-major fragments
__device__ __forceinline__ void ldsm_x4_t(uint32_t addr, uint32_t* r) {
    asm volatile("ldmatrix.sync.aligned.m8n8.x4.trans.shared.b16 {%0,%1,%2,%3}, [%4];"
                 : "=r"(r[0]), "=r"(r[1]), "=r"(r[2]), "=r"(r[3]) : "r"(addr));
}

__device__ __forceinline__ void mma_f16(float* d, const uint32_t* a, const uint32_t* b) {
    asm volatile("mma.sync.aligned.m16n8k16.row.col.f32.f16.f16.f32 "
                 "{%0,%1,%2,%3}, {%4,%5,%6,%7}, {%8,%9}, {%0,%1,%2,%3};"
                 : "+f"(d[0]), "+f"(d[1]), "+f"(d[2]), "+f"(d[3])
                 : "r"(a[0]), "r"(a[1]), "r"(a[2]), "r"(a[3]), "r"(b[0]), "r"(b[1]));
}

__device__ __forceinline__ void cp_async16(uint32_t dst, const void* src) {
    asm volatile("cp.async.cg.shared.global [%0], [%1], 16;" :: "r"(dst), "l"(src));
}
#define CP_COMMIT() asm volatile("cp.async.commit_group;" ::: "memory")
#define CP_WAIT1()  asm volatile("cp.async.wait_group 1;" ::: "memory")
#define CP_WAIT0()  asm volatile("cp.async.wait_group 0;" ::: "memory")

// ============================================================================
// Kernel 1 (fused prep): blocks [0,1536) wgen, [1536,2048) supports,
// [2048,6144) quant. All three are input-only and independent.
// ============================================================================
#define PREP_WGEN_BLOCKS  1536          // (NN/32) * ((KORD*CC*CC)/512) = 64*24
#define PREP_SUPP_BLOCKS  512           // NN/4
#define PREP_QUANT_BLOCKS 4096          // BB*NN*CC / (256*8)
#define PREP_BLOCKS (PREP_WGEN_BLOCKS + PREP_SUPP_BLOCKS + PREP_QUANT_BLOCKS)
#define PREP_SMEM   (DDIM * 512 * 4 + 32 * DDIM * 4)   // 34816 B

__global__ __launch_bounds__(256)
void prep_kernel(const float* __restrict__ X,
                 const float* __restrict__ E,
                 const float* __restrict__ Wp)
{
    extern __shared__ __align__(16) unsigned char dsm[];
    const int bid = blockIdx.x;
    const int t   = threadIdx.x;

    if (bid < PREP_WGEN_BLOCKS) {
        // ---------------- wgen: W[n,k,i,o] = sum_d E[n,d] * Wp[d,k,i,o] ----
        const int n0 = (bid / 24) * 32;
        const int c0 = (bid % 24) * 512;

        float (*WpS)[512] = reinterpret_cast<float(*)[512]>(dsm);
        float (*Es)[DDIM] = reinterpret_cast<float(*)[DDIM]>(dsm + DDIM * 512 * 4);
        const uint32_t dsmA = smem_u32(dsm);

        // Wp chunk via cp.async (8 x 16B per thread, all independent)
#pragma unroll
        for (int q = 0; q < 8; ++q) {
            const int idx = t + q * 256;
            const int d = idx >> 7, c4 = idx & 127;
            cp_async16(dsmA + (uint32_t)(d * 512 + c4 * 4) * 4,
                       Wp + (size_t)d * (KORD * CC * CC) + c0 + c4 * 4);
        }
        CP_COMMIT();
        if (t < 128) {
            const int nl = t >> 2, c4 = t & 3;
            float4 v = __ldg(reinterpret_cast<const float4*>(
                E + (size_t)(n0 + nl) * DDIM + c4 * 4));
            Es[nl][c4*4+0] = v.x; Es[nl][c4*4+1] = v.y;
            Es[nl][c4*4+2] = v.z; Es[nl][c4*4+3] = v.w;
        }
        CP_WAIT0();
        __syncthreads();

#pragma unroll 4
        for (int q = 0; q < 64; ++q) {
            const int idx = t + q * 256;
            const int nl = idx >> 9, c = idx & 511;
            float s = 0.f;
#pragma unroll
            for (int d = 0; d < DDIM; ++d)
                s = fmaf(Es[nl][d], WpS[d][c], s);
            g_Wh[(size_t)(n0 + nl) * (KORD * CC * CC) + c0 + c] = __float2half_rn(s);
        }
    } else if (bid < PREP_WGEN_BLOCKS + PREP_SUPP_BLOCKS) {
        // ---------------- supports: A = softmax(relu(E E^T)) -> fp16 -------
        const int n0   = (bid - PREP_WGEN_BLOCKS) * 4;
        const int lane = t & 31;
        const int wid  = t >> 5;

        __shared__ float esh[4][DDIM];
        __shared__ float red[4][8];

        if (t < 64) esh[t >> 4][t & 15] = E[(n0 + (t >> 4)) * DDIM + (t & 15)];
        __syncthreads();

        float z[4][8];
#pragma unroll
        for (int j = 0; j < 8; ++j) {
            const int m = j * 256 + t;
            const float4* em = reinterpret_cast<const float4*>(E + m * DDIM);
            float4 v0 = __ldg(em + 0), v1 = __ldg(em + 1);
            float4 v2 = __ldg(em + 2), v3 = __ldg(em + 3);
#pragma unroll
            for (int r = 0; r < 4; ++r) {
                float s = esh[r][0]*v0.x + esh[r][1]*v0.y + esh[r][2]*v0.z + esh[r][3]*v0.w
                        + esh[r][4]*v1.x + esh[r][5]*v1.y + esh[r][6]*v1.z + esh[r][7]*v1.w
                        + esh[r][8]*v2.x + esh[r][9]*v2.y + esh[r][10]*v2.z + esh[r][11]*v2.w
                        + esh[r][12]*v3.x + esh[r][13]*v3.y + esh[r][14]*v3.z + esh[r][15]*v3.w;
                z[r][j] = fmaxf(s, 0.f);
            }
        }

#pragma unroll
        for (int r = 0; r < 4; ++r) {
            float v = z[r][0];
#pragma unroll
            for (int j = 1; j < 8; ++j) v = fmaxf(v, z[r][j]);
#pragma unroll
            for (int off = 16; off; off >>= 1)
                v = fmaxf(v, __shfl_xor_sync(0xffffffffu, v, off));
            if (lane == 0) red[r][wid] = v;
        }
        __syncthreads();
        float mx4[4];
#pragma unroll
        for (int r = 0; r < 4; ++r) {
            float v = red[r][0];
#pragma unroll
            for (int w = 1; w < 8; ++w) v = fmaxf(v, red[r][w]);
            mx4[r] = v;
        }
        __syncthreads();

        float sum4[4];
#pragma unroll
        for (int r = 0; r < 4; ++r) {
            float s = 0.f;
#pragma unroll
            for (int j = 0; j < 8; ++j) { z[r][j] = __expf(z[r][j] - mx4[r]); s += z[r][j]; }
#pragma unroll
            for (int off = 16; off; off >>= 1)
                s += __shfl_xor_sync(0xffffffffu, s, off);
            if (lane == 0) red[r][wid] = s;
        }
        __syncthreads();
#pragma unroll
        for (int r = 0; r < 4; ++r) {
            float s = red[r][0];
#pragma unroll
            for (int w = 1; w < 8; ++w) s += red[r][w];
            sum4[r] = s;
        }

#pragma unroll
        for (int r = 0; r < 4; ++r) {
            const float inv = 1.0f / sum4[r];
#pragma unroll
            for (int j = 0; j < 8; ++j)
                g_Ah[(size_t)(n0 + r) * NN + j * 256 + t] = __float2half_rn(z[r][j] * inv);
        }
    } else {
        // ---------------- quant: X fp32 -> fp16, same layout ---------------
        const int qb = bid - (PREP_WGEN_BLOCKS + PREP_SUPP_BLOCKS);
        const size_t base = ((size_t)qb * 256 + t) * 8;
        float4 v0 = __ldg(reinterpret_cast<const float4*>(X + base));
        float4 v1 = __ldg(reinterpret_cast<const float4*>(X + base + 4));
        ushort4 h0;
        h0.x = __half_as_ushort(__float2half_rn(v0.x));
        h0.y = __half_as_ushort(__float2half_rn(v0.y));
        h0.z = __half_as_ushort(__float2half_rn(v0.z));
        h0.w = __half_as_ushort(__float2half_rn(v0.w));
        ushort4 h1;
        h1.x = __half_as_ushort(__float2half_rn(v1.x));
        h1.y = __half_as_ushort(__float2half_rn(v1.y));
        h1.z = __half_as_ushort(__float2half_rn(v1.z));
        h1.w = __half_as_ushort(__float2half_rn(v1.w));
        *reinterpret_cast<ushort4*>(g_Xh + base)     = h0;
        *reinterpret_cast<ushort4*>(g_Xh + base + 4) = h1;
    }
}

// ============================================================================
// Kernel 2 (x2): single-pass fp16 mma.sync GEMM, B via ldmatrix.trans.
//   Block 256(M) x 128(N = 2 batches) x 64(K); 512 threads / 16 warps,
//   warp tile 64x32, 3-stage cp.async pipeline.
// MODE 0: B = g_Xh,   out = g_XG1h fp16
// MODE 1: B = g_XG1h, out = g_XG2h = fp16(2*acc - fp16(X))
// ============================================================================
#define G_SROWB     144                     // A smem row bytes: 128 + 16 pad
#define G_AMAT      (256 * G_SROWB)         // 36864 B
#define B_SROWB     272                     // B smem row bytes: 256 + 16 pad
#define G_BMAT      (64 * B_SROWB)          // 17408 B
#define G_STAGE     (G_AMAT + G_BMAT)       // 54272 B
#define GEMM_SMEM   (3 * G_STAGE)           // 162816 B

template <int MODE>
__global__ __launch_bounds__(512, 1)
void gemm_kernel()
{
    extern __shared__ __align__(16) unsigned char smem_raw[];
    const uint32_t smem = smem_u32(smem_raw);

    const int tid  = threadIdx.x;
    const int lane = tid & 31;
    const int wid  = tid >> 5;
    const int m0   = blockIdx.x * 256;
    const int n0   = blockIdx.y * 128;
    const int b0   = blockIdx.y * 2;
    const int wm   = (wid >> 2) * 64;
    const int wn   = (wid & 3) * 32;

    const __half* __restrict__ Bhg = (MODE == 0) ? g_Xh : g_XG1h;

    float acc[4][4][4];
#pragma unroll
    for (int i = 0; i < 4; ++i)
#pragma unroll
        for (int j = 0; j < 4; ++j)
#pragma unroll
            for (int q = 0; q < 4; ++q) acc[i][j][q] = 0.f;

    auto issue = [&](int s) {
        const uint32_t sb = smem + (uint32_t)(s % 3) * G_STAGE;
        const int k0 = s * 64;
#pragma unroll
        for (int i = 0; i < 6; ++i) {
            const int idx = tid + i * 512;
            if (idx < 2048) {                      // A: rows 0..255, 8 chunks
                const int r = idx >> 3, c = idx & 7;
                cp_async16(sb + (uint32_t)(r * G_SROWB + c * 16),
                           g_Ah + (size_t)(m0 + r) * NN + k0 + c * 8);
            } else {                               // B: 64 k-rows x 16 chunks
                const int idx2 = idx - 2048;
                const int kl = idx2 >> 4;
                const int rem = idx2 & 15;
                const int b = rem >> 3, c8 = rem & 7;
                cp_async16(sb + (uint32_t)(G_AMAT + kl * B_SROWB + b * 128 + c8 * 16),
                           Bhg + ((size_t)(b0 + b) * NN + k0 + kl) * CC + c8 * 8);
            }
        }
        CP_COMMIT();
    };

    issue(0); issue(1);

    const uint32_t aRowB = (uint32_t)(wm + (lane & 15)) * G_SROWB
                         + (uint32_t)(lane >> 4) * 16;
    const uint32_t bRow  = (uint32_t)(lane & 15);
    const uint32_t bColB = (uint32_t)(wn + ((lane >> 4) << 3)) * 2;

    const int NT = NN / 64;   // 32

    for (int t = 0; t < NT; ++t) {
        CP_WAIT1();
        __syncthreads();

        const uint32_t sb = smem + (uint32_t)(t % 3) * G_STAGE;

        // ---- ks = 0 first, then overlap the next cp.async burst ----
        {
            uint32_t Af[4][4], Bf[2][4];
#pragma unroll
            for (int mt = 0; mt < 4; ++mt)
                ldsm_x4(sb + aRowB + (uint32_t)(mt * 16 * G_SROWB), Af[mt]);
#pragma unroll
            for (int bt = 0; bt < 2; ++bt)
                ldsm_x4_t(sb + G_AMAT + bRow * B_SROWB + bColB + (uint32_t)bt * 32, Bf[bt]);
#pragma unroll
            for (int mt = 0; mt < 4; ++mt)
#pragma unroll
                for (int nt = 0; nt < 4; ++nt)
                    mma_f16(acc[mt][nt], Af[mt], &Bf[nt >> 1][(nt & 1) * 2]);
        }

        if (t + 2 < NT) issue(t + 2);
        else CP_COMMIT();

#pragma unroll
        for (int ks = 1; ks < 4; ++ks) {
            const uint32_t kOff = (uint32_t)ks * 32;
            uint32_t Af[4][4], Bf[2][4];

#pragma unroll
            for (int mt = 0; mt < 4; ++mt)
                ldsm_x4(sb + aRowB + (uint32_t)(mt * 16 * G_SROWB) + kOff, Af[mt]);
#pragma unroll
            for (int bt = 0; bt < 2; ++bt)
                ldsm_x4_t(sb + G_AMAT + (uint32_t)(ks * 16 + bRow) * B_SROWB
                          + bColB + (uint32_t)bt * 32, Bf[bt]);
#pragma unroll
            for (int mt = 0; mt < 4; ++mt)
#pragma unroll
                for (int nt = 0; nt < 4; ++nt)
                    mma_f16(acc[mt][nt], Af[mt], &Bf[nt >> 1][(nt & 1) * 2]);
        }
    }

    // ---- epilogue: global fp16 writes ----
#pragma unroll
    for (int mt = 0; mt < 4; ++mt) {
        const int rloc = wm + mt * 16 + (lane >> 2);
        const int row  = m0 + rloc;
#pragma unroll
        for (int nt = 0; nt < 4; ++nt) {
            const int jloc = wn + nt * 8 + (lane & 3) * 2;
            const int j = n0 + jloc;
            const int b = j >> 6, c = j & 63;
            const size_t o0 = ((size_t)b * NN + row) * CC + c;
            const size_t o1 = ((size_t)b * NN + row + 8) * CC + c;
            if (MODE == 0) {
                *reinterpret_cast<__half2*>(g_XG1h + o0) =
                    __floats2half2_rn(acc[mt][nt][0], acc[mt][nt][1]);
                *reinterpret_cast<__half2*>(g_XG1h + o1) =
                    __floats2half2_rn(acc[mt][nt][2], acc[mt][nt][3]);
            } else {
                float2 x0 = __half22float2(*reinterpret_cast<const __half2*>(g_Xh + o0));
                float2 x1 = __half22float2(*reinterpret_cast<const __half2*>(g_Xh + o1));
                *reinterpret_cast<__half2*>(g_XG2h + o0) =
                    __floats2half2_rn(2.f * acc[mt][nt][0] - x0.x, 2.f * acc[mt][nt][1] - x0.y);
                *reinterpret_cast<__half2*>(g_XG2h + o1) =
                    __floats2half2_rn(2.f * acc[mt][nt][2] - x1.x, 2.f * acc[mt][nt][3] - x1.y);
            }
        }
    }
}

// ============================================================================
// Kernel 3: per-node contraction, single-pass fp16 tensor-core, cp.async loads.
// ============================================================================
#define F_SROW      200                    // Xs: fp16 per row (192 data + 8 pad)
#define F_XMATB     (64 * F_SROW * 2)      // 25600 B
#define F_WROWB     144                    // Ws row bytes: 128 data + 16 pad
#define F_WMATB     (192 * F_WROWB)        // 27648 B
#define FINAL_SMEM  (F_XMATB + F_WMATB)    // 53248 B

__global__ __launch_bounds__(256)
void final_kernel(const float* __restrict__ E,
                  const float* __restrict__ bp,
                  float* __restrict__ out)
{
    extern __shared__ __align__(16) unsigned char fsm_raw[];
    const uint32_t fsm = smem_u32(fsm_raw);
    const uint32_t XsA = fsm;               // [64 b][F_SROW i'] halves
    const uint32_t WsB = fsm + F_XMATB;     // [192 i'][64 o + pad] halves

    __shared__ float bias_s[CC];

    const int n    = blockIdx.x;
    const int tid  = threadIdx.x;
    const int lane = tid & 31;
    const int wid  = tid >> 5;

    // ---- Xcat: three fp16 sources via cp.async ----
    const __half* __restrict__ xsrcs[3] = { g_Xh, g_XG1h, g_XG2h };
#pragma unroll
    for (int k = 0; k < KORD; ++k) {
        const __half* __restrict__ hsrc = xsrcs[k];
#pragma unroll
        for (int i = 0; i < 2; ++i) {
            const int idx = tid + i * 256;
            const int b = idx >> 3, c8 = idx & 7;
            cp_async16(XsA + (uint32_t)(b * F_SROW + k * 64 + c8 * 8) * 2,
                       hsrc + ((size_t)b * NN + n) * CC + c8 * 8);
        }
    }
    // ---- W via cp.async into [i'][o] rows ----
#pragma unroll
    for (int k = 0; k < KORD; ++k) {
        const __half* wsrc = g_Wh + (size_t)n * (KORD * CC * CC) + (size_t)k * (CC * CC);
#pragma unroll
        for (int i = 0; i < 2; ++i) {
            const int idx = tid + i * 256;      // 64 ii x 8 chunks
            const int ii = idx >> 3, o8 = idx & 7;
            cp_async16(WsB + (uint32_t)((k * 64 + ii) * F_WROWB + o8 * 16),
                       wsrc + ii * 64 + o8 * 8);
        }
    }
    CP_COMMIT();

    if (tid < CC) {
        float s = 0.f;
#pragma unroll
        for (int d = 0; d < DDIM; ++d)
            s = fmaf(__ldg(E + (size_t)n * DDIM + d), __ldg(bp + d * CC + tid), s);
        bias_s[tid] = s;
    }
    CP_WAIT0();
    __syncthreads();

    const int wm    = (wid >> 1) * 16;     // b tile base
    const int obase = (wid & 1) * 32;      // o tile base

    const uint32_t aRowB = (uint32_t)(wm + (lane & 15)) * (F_SROW * 2)
                         + (uint32_t)(lane >> 4) * 16;
    const uint32_t bRow  = (uint32_t)(lane & 15);
    const uint32_t bColB = (uint32_t)(obase + ((lane >> 4) << 3)) * 2;

    float acc[4][4];
#pragma unroll
    for (int i = 0; i < 4; ++i)
#pragma unroll
        for (int q = 0; q < 4; ++q) acc[i][q] = 0.f;

#pragma unroll
    for (int step = 0; step < 12; ++step) {
        const uint32_t kOff = (uint32_t)step * 32;
        uint32_t Af[4], Bf[2][4];

        ldsm_x4(XsA + aRowB + kOff, Af);
#pragma unroll
        for (int bt = 0; bt < 2; ++bt)
            ldsm_x4_t(WsB + (uint32_t)(step * 16 + bRow) * F_WROWB
                      + bColB + (uint32_t)bt * 32, Bf[bt]);
#pragma unroll
        for (int nt = 0; nt < 4; ++nt)
            mma_f16(acc[nt], Af, &Bf[nt >> 1][(nt & 1) * 2]);
    }

    const int b0 = wm + (lane >> 2);
#pragma unroll
    for (int nt = 0; nt < 4; ++nt) {
        const int o = obase + nt * 8 + (lane & 3) * 2;
        const float bo0 = bias_s[o], bo1 = bias_s[o + 1];
        *reinterpret_cast<float2*>(out + ((size_t)b0 * NN + n) * CC + o) =
            make_float2(acc[nt][0] + bo0, acc[nt][1] + bo1);
        *reinterpret_cast<float2*>(out + ((size_t)(b0 + 8) * NN + n) * CC + o) =
            make_float2(acc[nt][2] + bo0, acc[nt][3] + bo1);
    }
}

// ============================================================================
// launch
// ============================================================================
extern "C" void kernel_launch(void* const* d_in, const int* in_sizes, int n_in,
                              void* d_out, int out_size)
{
    const float* X  = (const float*)d_in[0];
    const float* E  = (const float*)d_in[1];
    const float* Wp = (const float*)d_in[2];
    const float* bp = (const float*)d_in[3];
    float* out = (float*)d_out;

    cudaFuncSetAttribute(prep_kernel, cudaFuncAttributeMaxDynamicSharedMemorySize, PREP_SMEM);
    cudaFuncSetAttribute(gemm_kernel<0>, cudaFuncAttributeMaxDynamicSharedMemorySize, GEMM_SMEM);
    cudaFuncSetAttribute(gemm_kernel<1>, cudaFuncAttributeMaxDynamicSharedMemorySize, GEMM_SMEM);
    cudaFuncSetAttribute(final_kernel, cudaFuncAttributeMaxDynamicSharedMemorySize, FINAL_SMEM);

    // 1. fused prep: wgen + adjacency + X quantization (all input-only)
    prep_kernel<<<PREP_BLOCKS, 256, PREP_SMEM>>>(X, E, Wp);
    // 2. XG1 = A @ X
    gemm_kernel<0><<<dim3(NN / 256, BB / 2), 512, GEMM_SMEM>>>();
    // 3. XG2 = 2 A @ XG1 - X   (X correction from fp16 g_Xh)
    gemm_kernel<1><<<dim3(NN / 256, BB / 2), 512, GEMM_SMEM>>>();
    // 4. per-node contraction + bias (fp16 tensor cores, cp.async loads)
    final_kernel<<<NN, 256, FINAL_SMEM>>>(E, bp, out);
}